// round 1
// baseline (speedup 1.0000x reference)
#include <cuda_runtime.h>
#include <math.h>

// Problem constants (fixed shapes from reference)
#define BB 4
#define CC 256
#define CI 32
#define NN 4096
#define ROWS 320   // CI + CI + CC

// Scratch (device globals: no allocation allowed)
__device__ float g_Wcat[ROWS * CC];
__device__ float g_bcat[ROWS];
__device__ float g_QKV[(size_t)BB * ROWS * NN];   // 21 MB

// ---------------------------------------------------------------------------
// Kernel 0: concatenate weights/biases into one matrix [320, 256]
// ---------------------------------------------------------------------------
__global__ void prep_kernel(const float* __restrict__ Wq, const float* __restrict__ bq,
                            const float* __restrict__ Wk, const float* __restrict__ bk,
                            const float* __restrict__ Wv, const float* __restrict__ bv) {
    int i = blockIdx.x * blockDim.x + threadIdx.x;
    if (i < CI * CC)            g_Wcat[i] = Wq[i];
    else if (i < 2 * CI * CC)   g_Wcat[i] = Wk[i - CI * CC];
    else if (i < ROWS * CC)     g_Wcat[i] = Wv[i - 2 * CI * CC];
    if (i < CI)                 g_bcat[i] = bq[i];
    else if (i < 2 * CI)        g_bcat[i] = bk[i - CI];
    else if (i < ROWS)          g_bcat[i] = bv[i - 2 * CI];
}

// ---------------------------------------------------------------------------
// Kernel 1: QKV projection.  QKV[b][r][n] = sum_c Wcat[r][c] * x[b][c][n] + bcat[r]
// Tile: 64 rows x 128 cols, K-chunk 32. 256 threads, 4x8 microtile.
// ---------------------------------------------------------------------------
#define PBM 64
#define PBN 128
#define PBK 32

__global__ __launch_bounds__(256) void proj_kernel(const float* __restrict__ x) {
    __shared__ float ws[PBM][PBK + 1];     // 64 x 33
    __shared__ float xs[PBK][PBN + 4];     // 32 x 132 (float4-aligned rows)

    const int b = blockIdx.z;
    const int rowbase = blockIdx.y * PBM;
    const int nbase = blockIdx.x * PBN;
    const int tid = threadIdx.x;
    const int tr = tid >> 4;       // 0..15 -> rows tr*4 .. tr*4+3
    const int tc = tid & 15;       // 0..15 -> cols tc*8 .. tc*8+7

    const float* xb = x + (size_t)b * CC * NN;

    float acc[4][8];
#pragma unroll
    for (int i = 0; i < 4; i++)
#pragma unroll
        for (int j = 0; j < 8; j++) acc[i][j] = 0.f;

    for (int kc = 0; kc < CC; kc += PBK) {
#pragma unroll
        for (int i = 0; i < 8; i++) {
            int idx = tid + i * 256;
            int r = idx >> 5, c = idx & 31;
            ws[r][c] = g_Wcat[(rowbase + r) * CC + kc + c];
        }
#pragma unroll
        for (int i = 0; i < 16; i++) {
            int idx = tid + i * 256;
            int r = idx >> 7, c = idx & 127;
            xs[r][c] = xb[(size_t)(kc + r) * NN + nbase + c];
        }
        __syncthreads();

#pragma unroll
        for (int kk = 0; kk < PBK; kk++) {
            float a0 = ws[tr * 4 + 0][kk];
            float a1 = ws[tr * 4 + 1][kk];
            float a2 = ws[tr * 4 + 2][kk];
            float a3 = ws[tr * 4 + 3][kk];
            float4 b0 = *(const float4*)&xs[kk][tc * 8];
            float4 b1 = *(const float4*)&xs[kk][tc * 8 + 4];
            float bb[8] = {b0.x, b0.y, b0.z, b0.w, b1.x, b1.y, b1.z, b1.w};
#pragma unroll
            for (int j = 0; j < 8; j++) {
                acc[0][j] += a0 * bb[j];
                acc[1][j] += a1 * bb[j];
                acc[2][j] += a2 * bb[j];
                acc[3][j] += a3 * bb[j];
            }
        }
        __syncthreads();
    }

#pragma unroll
    for (int i = 0; i < 4; i++) {
        int r = rowbase + tr * 4 + i;
        float bias = g_bcat[r];
        float* dst = g_QKV + ((size_t)b * ROWS + r) * NN + nbase + tc * 8;
#pragma unroll
        for (int j = 0; j < 8; j++) dst[j] = acc[i][j] + bias;
    }
}

// ---------------------------------------------------------------------------
// Kernel 2: fused flash attention + epilogue.
// One CTA = one (batch, 64-query tile). Online softmax over 64-key tiles.
// Thread layout: tr = tid>>4 (4 query rows tr*4+i), tc = tid&15
//   S microtile: 4 x 4 (cols tc*4+j)
//   O microtile: 4 q x 16 channels, channels interleaved c = tc + 16*j
// ---------------------------------------------------------------------------
#define BQ 64
#define BK2 64
#define QS_STRIDE 68   // 32 x 68   (float4 aligned, conflict-free)
#define SS_STRIDE 65   // 64 x 65
#define VS_STRIDE 65   // 256 x 65

#define SM_QS 0
#define SM_KS (SM_QS + 32 * QS_STRIDE)
#define SM_SS (SM_KS + 32 * QS_STRIDE)
#define SM_VS (SM_SS + BQ * SS_STRIDE)
#define SM_RMAX (SM_VS + CC * VS_STRIDE)
#define SM_RSUM (SM_RMAX + BQ)
#define SM_RALPHA (SM_RSUM + BQ)
#define SM_TOTAL (SM_RALPHA + BQ)

extern __shared__ float sm[];

__global__ __launch_bounds__(256) void attn_kernel(const float* __restrict__ x,
                                                   const float* __restrict__ gamma_p,
                                                   float* __restrict__ out) {
    float* Qs = sm + SM_QS;
    float* Ks = sm + SM_KS;
    float* Ss = sm + SM_SS;
    float* Vs = sm + SM_VS;
    float* rmax = sm + SM_RMAX;
    float* rsum = sm + SM_RSUM;
    float* ralpha = sm + SM_RALPHA;

    const int b = blockIdx.y;
    const int qbase = blockIdx.x * BQ;
    const int tid = threadIdx.x;
    const int tr = tid >> 4;
    const int tc = tid & 15;

    const float* Qg = g_QKV + (size_t)b * ROWS * NN;            // rows 0..31
    const float* Kg = Qg + (size_t)CI * NN;                     // rows 32..63
    const float* Vg = Qg + (size_t)2 * CI * NN;                 // rows 64..319

    // Load Q tile transposed: Qs[c][q]
    for (int i = tid; i < 32 * BQ; i += 256) {
        int c = i >> 6, q = i & 63;
        Qs[c * QS_STRIDE + q] = Qg[(size_t)c * NN + qbase + q];
    }
    if (tid < BQ) { rmax[tid] = -1e30f; rsum[tid] = 0.f; }

    float acc[4][16];
#pragma unroll
    for (int i = 0; i < 4; i++)
#pragma unroll
        for (int j = 0; j < 16; j++) acc[i][j] = 0.f;

    __syncthreads();

    for (int kt = 0; kt < NN; kt += BK2) {
        // stage K tile (32x64) and V tile (256x64)
        for (int i = tid; i < 32 * BK2; i += 256) {
            int c = i >> 6, m = i & 63;
            Ks[c * QS_STRIDE + m] = Kg[(size_t)c * NN + kt + m];
        }
        for (int i = tid; i < CC * BK2; i += 256) {
            int c = i >> 6, m = i & 63;
            Vs[c * VS_STRIDE + m] = Vg[(size_t)c * NN + kt + m];
        }
        __syncthreads();

        // S = Q^T K  (4x4 microtile per thread)
        float s[4][4];
#pragma unroll
        for (int i = 0; i < 4; i++)
#pragma unroll
            for (int j = 0; j < 4; j++) s[i][j] = 0.f;

#pragma unroll
        for (int c = 0; c < 32; c++) {
            float4 qv = *(const float4*)&Qs[c * QS_STRIDE + tr * 4];
            float4 kv = *(const float4*)&Ks[c * QS_STRIDE + tc * 4];
            float qa[4] = {qv.x, qv.y, qv.z, qv.w};
            float ka[4] = {kv.x, kv.y, kv.z, kv.w};
#pragma unroll
            for (int i = 0; i < 4; i++)
#pragma unroll
                for (int j = 0; j < 4; j++) s[i][j] += qa[i] * ka[j];
        }
#pragma unroll
        for (int i = 0; i < 4; i++)
#pragma unroll
            for (int j = 0; j < 4; j++)
                Ss[(tr * 4 + i) * SS_STRIDE + tc * 4 + j] = s[i][j];
        __syncthreads();

        // Online softmax over this tile: 4 lanes per row
        {
            int row = tid >> 2, sub = tid & 3;
            float* srow = &Ss[row * SS_STRIDE + sub * 16];
            float tm = -1e30f;
#pragma unroll
            for (int m = 0; m < 16; m++) tm = fmaxf(tm, srow[m]);
            tm = fmaxf(tm, __shfl_xor_sync(0xffffffffu, tm, 1));
            tm = fmaxf(tm, __shfl_xor_sync(0xffffffffu, tm, 2));
            float mold = rmax[row];
            float mnew = fmaxf(mold, tm);
            float lsum = 0.f;
#pragma unroll
            for (int m = 0; m < 16; m++) {
                float p = __expf(srow[m] - mnew);
                srow[m] = p;
                lsum += p;
            }
            lsum += __shfl_xor_sync(0xffffffffu, lsum, 1);
            lsum += __shfl_xor_sync(0xffffffffu, lsum, 2);
            if (sub == 0) {
                float alpha = __expf(mold - mnew);
                ralpha[row] = alpha;
                rsum[row] = rsum[row] * alpha + lsum;
                rmax[row] = mnew;
            }
        }
        __syncthreads();

        // rescale accumulator, then O += P * V^T
        float al[4];
#pragma unroll
        for (int i = 0; i < 4; i++) al[i] = ralpha[tr * 4 + i];
#pragma unroll
        for (int i = 0; i < 4; i++)
#pragma unroll
            for (int j = 0; j < 16; j++) acc[i][j] *= al[i];

        for (int m = 0; m < BK2; m++) {
            float p[4];
#pragma unroll
            for (int i = 0; i < 4; i++) p[i] = Ss[(tr * 4 + i) * SS_STRIDE + m];
#pragma unroll
            for (int j = 0; j < 16; j++) {
                float v = Vs[(tc + 16 * j) * VS_STRIDE + m];
#pragma unroll
                for (int i = 0; i < 4; i++) acc[i][j] += p[i] * v;
            }
        }
        __syncthreads();
    }

    // Epilogue: out = gamma * O / l + x
    float gamma = gamma_p[0];
    float rl[4];
#pragma unroll
    for (int i = 0; i < 4; i++) rl[i] = 1.0f / rsum[tr * 4 + i];

    const float* xb = x + (size_t)b * CC * NN;
    float* ob = out + (size_t)b * CC * NN;
#pragma unroll
    for (int j = 0; j < 16; j++) {
        int c = tc + 16 * j;
#pragma unroll
        for (int i = 0; i < 4; i++) {
            int n = qbase + tr * 4 + i;
            size_t idx = (size_t)c * NN + n;
            ob[idx] = gamma * acc[i][j] * rl[i] + xb[idx];
        }
    }
}

// ---------------------------------------------------------------------------
// Launch
// ---------------------------------------------------------------------------
extern "C" void kernel_launch(void* const* d_in, const int* in_sizes, int n_in,
                              void* d_out, int out_size) {
    const float* x  = (const float*)d_in[0];
    const float* Wq = (const float*)d_in[1];
    const float* bq = (const float*)d_in[2];
    const float* Wk = (const float*)d_in[3];
    const float* bk = (const float*)d_in[4];
    const float* Wv = (const float*)d_in[5];
    const float* bv = (const float*)d_in[6];
    const float* gamma = (const float*)d_in[7];
    float* out = (float*)d_out;

    // 0) concat weights
    prep_kernel<<<(ROWS * CC + 255) / 256, 256>>>(Wq, bq, Wk, bk, Wv, bv);

    // 1) QKV projection: grid (ncols, rowgroups, batch)
    dim3 pgrid(NN / PBN, ROWS / PBM, BB);
    proj_kernel<<<pgrid, 256>>>(x);

    // 2) fused attention
    static int smem_set = 0;
    size_t smem_bytes = (size_t)SM_TOTAL * sizeof(float);
    if (!smem_set) {
        cudaFuncSetAttribute(attn_kernel, cudaFuncAttributeMaxDynamicSharedMemorySize,
                             (int)smem_bytes);
        smem_set = 1;
    }
    dim3 agrid(NN / BQ, BB);
    attn_kernel<<<agrid, 256, smem_bytes>>>(x, gamma, out);
}

// round 3
// speedup vs baseline: 3.8718x; 3.8718x over previous
#include <cuda_runtime.h>
#include <cstdint>
#include <math.h>

// Problem constants
#define BB 4
#define CC 256
#define CI 32
#define NN 4096
#define ROWS 320   // CI + CI + CC

// Scratch
__device__ float g_Wcat[ROWS * CC];
__device__ float g_bcat[ROWS];
__device__ float g_QKV[(size_t)BB * ROWS * NN];

// ===========================================================================
// Helpers (arch-portable PTX only: sm_80-era)
// ===========================================================================
__device__ __forceinline__ uint32_t smem_to_u32(const void* p) {
    uint32_t a;
    asm("{ .reg .u64 t; cvta.to.shared.u64 t, %1; cvt.u32.u64 %0, t; }" : "=r"(a) : "l"(p));
    return a;
}
__device__ __forceinline__ uint32_t f2tf(float f) {
    uint32_t r; asm("cvt.rna.tf32.f32 %0, %1;" : "=r"(r) : "f"(f)); return r;
}
__device__ __forceinline__ void cp16(uint32_t dst, const void* src) {
    asm volatile("cp.async.ca.shared.global [%0], [%1], 16;" :: "r"(dst), "l"(src) : "memory");
}
#define CP_COMMIT() asm volatile("cp.async.commit_group;" ::: "memory")
#define CP_WAIT(n)  asm volatile("cp.async.wait_group %0;" :: "n"(n) : "memory")

// D[16x8] += A[16x8] * B[8x8], tf32 inputs, f32 accum.  (HMMA fallback path)
__device__ __forceinline__ void mma_tf32(float* d, const uint32_t* a, uint32_t b0, uint32_t b1) {
    asm volatile(
        "mma.sync.aligned.m16n8k8.row.col.f32.tf32.tf32.f32 "
        "{%0,%1,%2,%3}, {%4,%5,%6,%7}, {%8,%9}, {%0,%1,%2,%3};"
        : "+f"(d[0]), "+f"(d[1]), "+f"(d[2]), "+f"(d[3])
        : "r"(a[0]), "r"(a[1]), "r"(a[2]), "r"(a[3]), "r"(b0), "r"(b1));
}

// ===========================================================================
// Kernel 0: concat weights
// ===========================================================================
__global__ void prep_kernel(const float* __restrict__ Wq, const float* __restrict__ bq,
                            const float* __restrict__ Wk, const float* __restrict__ bk,
                            const float* __restrict__ Wv, const float* __restrict__ bv) {
    int i = blockIdx.x * blockDim.x + threadIdx.x;
    if (i < CI * CC)            g_Wcat[i] = Wq[i];
    else if (i < 2 * CI * CC)   g_Wcat[i] = Wk[i - CI * CC];
    else if (i < ROWS * CC)     g_Wcat[i] = Wv[i - 2 * CI * CC];
    if (i < CI)                 g_bcat[i] = bq[i];
    else if (i < 2 * CI)        g_bcat[i] = bk[i - CI];
    else if (i < ROWS)          g_bcat[i] = bv[i - 2 * CI];
}

// ===========================================================================
// Kernel 1: QKV projection (scalar fp32)
// ===========================================================================
#define PBM 64
#define PBN 128
#define PBK 32
__global__ __launch_bounds__(256) void proj_kernel(const float* __restrict__ x) {
    __shared__ float ws[PBM][PBK + 1];
    __shared__ float xs[PBK][PBN + 4];
    const int b = blockIdx.z;
    const int rowbase = blockIdx.y * PBM;
    const int nbase = blockIdx.x * PBN;
    const int tid = threadIdx.x;
    const int tr = tid >> 4, tc = tid & 15;
    const float* xb = x + (size_t)b * CC * NN;
    float acc[4][8];
#pragma unroll
    for (int i = 0; i < 4; i++)
#pragma unroll
        for (int j = 0; j < 8; j++) acc[i][j] = 0.f;
    for (int kc = 0; kc < CC; kc += PBK) {
#pragma unroll
        for (int i = 0; i < 8; i++) {
            int idx = tid + i * 256;
            ws[idx >> 5][idx & 31] = g_Wcat[(rowbase + (idx >> 5)) * CC + kc + (idx & 31)];
        }
#pragma unroll
        for (int i = 0; i < 16; i++) {
            int idx = tid + i * 256;
            xs[idx >> 7][idx & 127] = xb[(size_t)(kc + (idx >> 7)) * NN + nbase + (idx & 127)];
        }
        __syncthreads();
#pragma unroll
        for (int kk = 0; kk < PBK; kk++) {
            float a0 = ws[tr * 4 + 0][kk], a1 = ws[tr * 4 + 1][kk];
            float a2 = ws[tr * 4 + 2][kk], a3 = ws[tr * 4 + 3][kk];
            float4 b0 = *(const float4*)&xs[kk][tc * 8];
            float4 b1 = *(const float4*)&xs[kk][tc * 8 + 4];
            float bbv[8] = {b0.x, b0.y, b0.z, b0.w, b1.x, b1.y, b1.z, b1.w};
#pragma unroll
            for (int j = 0; j < 8; j++) {
                acc[0][j] += a0 * bbv[j]; acc[1][j] += a1 * bbv[j];
                acc[2][j] += a2 * bbv[j]; acc[3][j] += a3 * bbv[j];
            }
        }
        __syncthreads();
    }
#pragma unroll
    for (int i = 0; i < 4; i++) {
        int r = rowbase + tr * 4 + i;
        float bias = g_bcat[r];
        float* dst = g_QKV + ((size_t)b * ROWS + r) * NN + nbase + tc * 8;
#pragma unroll
        for (int j = 0; j < 8; j++) dst[j] = acc[i][j] + bias;
    }
}

// ===========================================================================
// Kernel 2: flash attention via mma.sync tf32 (m16n8k8).
// CTA = (batch, 128-q tile). 8 warps / 256 threads.
//   S phase:  warp w owns q rows [16w,16w+16); K smem [c][m] stride 72
//   PV phase: warp w owns channels [32w,32w+32); V smem [ch][m] stride 68
//   P smem [q][m] stride 68, tf32-rounded at write.
// K/V double-buffered, staged with cp.async (overlaps compute of prev tile).
// No max-subtraction softmax (|S| <~ 10): l is pure register accumulation.
// ===========================================================================
#define BQ 128
#define BK 64
#define NT (NN / BK)

#define KST 72
#define VST 68
#define PST 68
// float offsets
#define KO0 0
#define KO1 (32 * KST)                 // 2304
#define VO0 (2 * 32 * KST)             // 4608
#define VO1 (VO0 + 256 * VST)          // 22016
#define PO  (VO1 + 256 * VST)          // 39424
#define LO  (PO + BQ * PST)            // 48128
#define SMF (LO + BQ)                  // 48256 floats = 193024 B

__device__ __forceinline__ void stage_tile(uint32_t sb, int buf, int kt,
                                           const float* __restrict__ Kg,
                                           const float* __restrict__ Vg, int tid) {
    uint32_t kdst = sb + (buf ? KO1 : KO0) * 4;
    uint32_t vdst = sb + (buf ? VO1 : VO0) * 4;
#pragma unroll
    for (int r = 0; r < 2; r++) {           // K: 32 rows x 64 floats
        int idx = tid + r * 256;
        int c = idx >> 4, j = idx & 15;
        cp16(kdst + c * (KST * 4) + j * 16, Kg + (size_t)c * NN + kt + j * 4);
    }
#pragma unroll
    for (int r = 0; r < 16; r++) {          // V: 256 rows x 64 floats
        int idx = tid + r * 256;
        int ch = idx >> 4, j = idx & 15;
        cp16(vdst + ch * (VST * 4) + j * 16, Vg + (size_t)ch * NN + kt + j * 4);
    }
}

__global__ __launch_bounds__(256, 1) void attn_tc(const float* __restrict__ x,
                                                  const float* __restrict__ gamma_p,
                                                  float* __restrict__ out) {
    extern __shared__ float smf[];
    const uint32_t sb = smem_to_u32(smf);
    const int tid = threadIdx.x;
    const int w = tid >> 5;
    const int lane = tid & 31;
    const int lq = lane >> 2;     // 0..7
    const int lt4 = lane & 3;     // 0..3
    const int b = blockIdx.y;
    const int qbase = blockIdx.x * BQ;

    const float* Qg = g_QKV + (size_t)b * ROWS * NN;
    const float* Kg = Qg + (size_t)CI * NN;
    const float* Vg = Qg + (size_t)2 * CI * NN;

    // stage tile 0
    stage_tile(sb, 0, 0, Kg, Vg, tid);
    CP_COMMIT();

    // Q A-fragments (held in registers for whole kernel)
    uint32_t aq[4][4];
    {
        const int q0 = qbase + w * 16 + lq;
#pragma unroll
        for (int ks = 0; ks < 4; ks++) {
            int c = ks * 8 + lt4;
            aq[ks][0] = f2tf(Qg[(size_t)c * NN + q0]);
            aq[ks][1] = f2tf(Qg[(size_t)c * NN + q0 + 8]);
            aq[ks][2] = f2tf(Qg[(size_t)(c + 4) * NN + q0]);
            aq[ks][3] = f2tf(Qg[(size_t)(c + 4) * NN + q0 + 8]);
        }
    }

    float Oacc[128];
#pragma unroll
    for (int i = 0; i < 128; i++) Oacc[i] = 0.f;
    float l0 = 0.f, l1 = 0.f;
    const int r0 = w * 16 + lq;

#pragma unroll 1
    for (int t = 0; t < NT; t++) {
        const int bi = t & 1;
        __syncthreads();   // prev tile's PV / P reads done -> buffers reusable
        if (t + 1 < NT) {
            stage_tile(sb, (t + 1) & 1, (t + 1) * BK, Kg, Vg, tid);
            CP_COMMIT();
            CP_WAIT(1);    // tile t's copies complete
        } else {
            CP_WAIT(0);
        }
        __syncthreads();   // staged data visible to all warps

        // ---- S = Q K^T for this warp's 16 rows
        const float* kb = smf + (bi ? KO1 : KO0);
        float sacc[8][4];
#pragma unroll
        for (int nt = 0; nt < 8; nt++)
#pragma unroll
            for (int e = 0; e < 4; e++) sacc[nt][e] = 0.f;
#pragma unroll
        for (int ks = 0; ks < 4; ks++) {
            const float* krow0 = kb + (ks * 8 + lt4) * KST + lq;
            const float* krow1 = krow0 + 4 * KST;
#pragma unroll
            for (int nt = 0; nt < 8; nt++) {
                uint32_t b0 = f2tf(krow0[nt * 8]);
                uint32_t b1 = f2tf(krow1[nt * 8]);
                mma_tf32(sacc[nt], aq[ks], b0, b1);
            }
        }

        // ---- softmax (no max subtraction) + write P (tf32-rounded)
        float* pB = smf + PO;
#pragma unroll
        for (int nt = 0; nt < 8; nt++) {
            float p0 = __expf(sacc[nt][0]);
            float p1 = __expf(sacc[nt][1]);
            float p2 = __expf(sacc[nt][2]);
            float p3 = __expf(sacc[nt][3]);
            l0 += p0 + p1;
            l1 += p2 + p3;
            float2 v01 = make_float2(__uint_as_float(f2tf(p0)), __uint_as_float(f2tf(p1)));
            float2 v23 = make_float2(__uint_as_float(f2tf(p2)), __uint_as_float(f2tf(p3)));
            *(float2*)&pB[r0 * PST + nt * 8 + 2 * lt4] = v01;
            *(float2*)&pB[(r0 + 8) * PST + nt * 8 + 2 * lt4] = v23;
        }
        __syncthreads();   // P visible to all warps

        // ---- O += P V^T   (warp w: channels 32w..32w+31)
        const float* vb = smf + (bi ? VO1 : VO0) + (w * 32) * VST;
#pragma unroll
        for (int ks = 0; ks < 8; ks++) {
            uint32_t v0[4], v1[4];
#pragma unroll
            for (int nt = 0; nt < 4; nt++) {
                const float* vp = vb + (nt * 8 + lq) * VST + ks * 8 + lt4;
                v0[nt] = f2tf(vp[0]);
                v1[nt] = f2tf(vp[4]);
            }
#pragma unroll
            for (int mt = 0; mt < 8; mt++) {
                const float* pp = pB + (mt * 16 + lq) * PST + ks * 8 + lt4;
                uint32_t a[4];
                a[0] = __float_as_uint(pp[0]);
                a[1] = __float_as_uint(pp[8 * PST]);
                a[2] = __float_as_uint(pp[4]);
                a[3] = __float_as_uint(pp[8 * PST + 4]);
#pragma unroll
                for (int nt = 0; nt < 4; nt++)
                    mma_tf32(&Oacc[(mt * 4 + nt) * 4], a, v0[nt], v1[nt]);
            }
        }
    }

    // ---- epilogue
    l0 += __shfl_xor_sync(0xffffffffu, l0, 1);
    l0 += __shfl_xor_sync(0xffffffffu, l0, 2);
    l1 += __shfl_xor_sync(0xffffffffu, l1, 1);
    l1 += __shfl_xor_sync(0xffffffffu, l1, 2);
    if (lt4 == 0) {
        smf[LO + r0] = l0;
        smf[LO + r0 + 8] = l1;
    }
    __syncthreads();

    const float g = gamma_p[0];
    const float* xb = x + (size_t)b * CC * NN;
    float* ob = out + (size_t)b * CC * NN;
#pragma unroll
    for (int mt = 0; mt < 8; mt++) {
        int qa = mt * 16 + lq;
        float sa = g / smf[LO + qa];
        float sb2 = g / smf[LO + qa + 8];
        int na = qbase + qa;
        int nb = na + 8;
#pragma unroll
        for (int nt = 0; nt < 4; nt++) {
            int ch = w * 32 + nt * 8 + 2 * lt4;
            const float* o = &Oacc[(mt * 4 + nt) * 4];
            size_t i00 = (size_t)ch * NN + na;
            size_t i10 = (size_t)(ch + 1) * NN + na;
            ob[i00] = o[0] * sa + xb[i00];
            ob[i10] = o[1] * sa + xb[i10];
            ob[i00 + 8] = o[2] * sb2 + xb[i00 + 8];
            ob[i10 + 8] = o[3] * sb2 + xb[i10 + 8];
        }
    }
}

// ===========================================================================
// Launch
// ===========================================================================
extern "C" void kernel_launch(void* const* d_in, const int* in_sizes, int n_in,
                              void* d_out, int out_size) {
    const float* x  = (const float*)d_in[0];
    const float* Wq = (const float*)d_in[1];
    const float* bq = (const float*)d_in[2];
    const float* Wk = (const float*)d_in[3];
    const float* bk = (const float*)d_in[4];
    const float* Wv = (const float*)d_in[5];
    const float* bv = (const float*)d_in[6];
    const float* gamma = (const float*)d_in[7];
    float* out = (float*)d_out;

    prep_kernel<<<(ROWS * CC + 255) / 256, 256>>>(Wq, bq, Wk, bk, Wv, bv);

    dim3 pgrid(NN / PBN, ROWS / PBM, BB);
    proj_kernel<<<pgrid, 256>>>(x);

    static int smem_set = 0;
    if (!smem_set) {
        cudaFuncSetAttribute(attn_tc, cudaFuncAttributeMaxDynamicSharedMemorySize,
                             SMF * (int)sizeof(float));
        smem_set = 1;
    }
    dim3 agrid(NN / BQ, BB);
    attn_tc<<<agrid, 256, SMF * sizeof(float)>>>(x, gamma, out);
}

// round 4
// speedup vs baseline: 7.8724x; 2.0332x over previous
#include <cuda_runtime.h>
#include <cuda_fp16.h>
#include <cstdint>
#include <math.h>

#define BB 4
#define CC 256
#define CI 32
#define NN 4096
#define ROWS 320

__device__ float g_bcat[ROWS];
__device__ __align__(256) __half g_W16[ROWS * CC];
__device__ __align__(256) __half g_xT[(size_t)BB * NN * CC];
__device__ __align__(256) __half g_QKV16[(size_t)BB * ROWS * NN];

// ===========================================================================
// Portable PTX helpers (sm_75/80-era, valid under compute_103)
// ===========================================================================
__device__ __forceinline__ uint32_t smem_to_u32(const void* p) {
    uint32_t a;
    asm("{ .reg .u64 t; cvta.to.shared.u64 t, %1; cvt.u32.u64 %0, t; }" : "=r"(a) : "l"(p));
    return a;
}
__device__ __forceinline__ void cp16(uint32_t dst, const void* src) {
    asm volatile("cp.async.ca.shared.global [%0], [%1], 16;" :: "r"(dst), "l"(src) : "memory");
}
#define CP_COMMIT() asm volatile("cp.async.commit_group;" ::: "memory")
#define CP_WAIT(n)  asm volatile("cp.async.wait_group %0;" :: "n"(n) : "memory")

__device__ __forceinline__ void ldsm_x4(uint32_t* r, uint32_t addr) {
    asm volatile("ldmatrix.sync.aligned.m8n8.x4.shared.b16 {%0,%1,%2,%3}, [%4];"
        : "=r"(r[0]), "=r"(r[1]), "=r"(r[2]), "=r"(r[3]) : "r"(addr));
}
__device__ __forceinline__ void ldsm_x4t(uint32_t* r, uint32_t addr) {
    asm volatile("ldmatrix.sync.aligned.m8n8.x4.trans.shared.b16 {%0,%1,%2,%3}, [%4];"
        : "=r"(r[0]), "=r"(r[1]), "=r"(r[2]), "=r"(r[3]) : "r"(addr));
}
// D[16x8] += A[16x16] * B[16x8], fp16 in, fp32 accum
__device__ __forceinline__ void mma16(float* d, const uint32_t* a, uint32_t b0, uint32_t b1) {
    asm volatile(
        "mma.sync.aligned.m16n8k16.row.col.f32.f16.f16.f32 "
        "{%0,%1,%2,%3}, {%4,%5,%6,%7}, {%8,%9}, {%0,%1,%2,%3};"
        : "+f"(d[0]), "+f"(d[1]), "+f"(d[2]), "+f"(d[3])
        : "r"(a[0]), "r"(a[1]), "r"(a[2]), "r"(a[3]), "r"(b0), "r"(b1));
}

// ===========================================================================
// Kernel 0: concat + fp16-convert weights
// ===========================================================================
__global__ void prep_kernel(const float* __restrict__ Wq, const float* __restrict__ bq,
                            const float* __restrict__ Wk, const float* __restrict__ bk,
                            const float* __restrict__ Wv, const float* __restrict__ bv) {
    int i = blockIdx.x * blockDim.x + threadIdx.x;
    if (i < CI * CC)            g_W16[i] = __float2half(Wq[i]);
    else if (i < 2 * CI * CC)   g_W16[i] = __float2half(Wk[i - CI * CC]);
    else if (i < ROWS * CC)     g_W16[i] = __float2half(Wv[i - 2 * CI * CC]);
    if (i < CI)                 g_bcat[i] = bq[i];
    else if (i < 2 * CI)        g_bcat[i] = bk[i - CI];
    else if (i < ROWS)          g_bcat[i] = bv[i - 2 * CI];
}

// ===========================================================================
// Kernel 1: transpose+convert x[b][c][n] fp32 -> g_xT[b][n][c] fp16
// ===========================================================================
__global__ void convx_kernel(const float* __restrict__ x) {
    __shared__ __half t[32][33];
    const int b = blockIdx.z, nb = blockIdx.x * 32, cb = blockIdx.y * 32;
    const int tx = threadIdx.x, ty = threadIdx.y;
    const float* xb = x + (size_t)b * CC * NN;
#pragma unroll
    for (int i = 0; i < 4; i++)
        t[ty + i * 8][tx] = __float2half(xb[(size_t)(cb + ty + i * 8) * NN + nb + tx]);
    __syncthreads();
    __half* dst = g_xT + (size_t)b * NN * CC;
#pragma unroll
    for (int i = 0; i < 4; i++)
        dst[(size_t)(nb + ty + i * 8) * CC + cb + tx] = t[tx][ty + i * 8];
}

// ===========================================================================
// Kernel 2: QKV projection via fp16 mma.  C[320x4096] = W16[320x256] x X[256x4096]
// Tile M=64 x N=256, K chunks of 64, double-buffered cp.async.
// ===========================================================================
#define WSTH 264          // halves; 528B rows (132 words -> 4r mod 32, conflict-free)
#define XSTH 72           // halves; 144B rows (36 words  -> 4r mod 32)
#define PJ_WS 0
#define PJ_X0 33792
#define PJ_X1 70656
#define PJ_SMEM 107520

__global__ __launch_bounds__(256) void proj_kernel() {
    extern __shared__ __align__(128) char psm[];
    const uint32_t sb = smem_to_u32(psm);
    const int tid = threadIdx.x;
    const int w = tid >> 5, lane = tid & 31;
    const int lq = lane >> 2, lt4 = lane & 3;
    const int wm = w & 3, wn = w >> 2;
    const int b = blockIdx.z;
    const int rowbase = blockIdx.y * 64;
    const int nbase = blockIdx.x * 256;

    // stage W tile (whole K=256) once
    const __half* Wg = g_W16 + (size_t)rowbase * CC;
#pragma unroll
    for (int i = 0; i < 8; i++) {
        int idx = tid + i * 256, r = idx >> 5, ch = idx & 31;
        cp16(sb + PJ_WS + r * 528 + ch * 16, Wg + (size_t)r * CC + ch * 8);
    }
    const __half* Xg = g_xT + ((size_t)b * NN + nbase) * CC;
    // stage X chunk 0
#pragma unroll
    for (int i = 0; i < 8; i++) {
        int idx = tid + i * 256, n = idx >> 3, j = idx & 7;
        cp16(sb + PJ_X0 + n * 144 + j * 16, Xg + (size_t)n * CC + j * 8);
    }
    CP_COMMIT();

    float acc[16][4];
#pragma unroll
    for (int i = 0; i < 16; i++)
#pragma unroll
        for (int e = 0; e < 4; e++) acc[i][e] = 0.f;

    const uint32_t aoffL = (uint32_t)((wm * 16 + (lane & 15)) * 528 + (lane >> 4) * 16);
    const uint32_t boffL = (uint32_t)((((lane >> 3) & 1) * 8 + (lane & 7)) * 144 + (lane >> 4) * 16);

#pragma unroll
    for (int kc = 0; kc < 4; kc++) {
        if (kc + 1 < 4) {
            uint32_t xdst = sb + ((kc + 1) & 1 ? PJ_X1 : PJ_X0);
#pragma unroll
            for (int i = 0; i < 8; i++) {
                int idx = tid + i * 256, n = idx >> 3, j = idx & 7;
                cp16(xdst + n * 144 + j * 16, Xg + (size_t)n * CC + (kc + 1) * 64 + j * 8);
            }
            CP_COMMIT();
            CP_WAIT(1);
        } else {
            CP_WAIT(0);
        }
        __syncthreads();
        const uint32_t xb32 = sb + (kc & 1 ? PJ_X1 : PJ_X0);
#pragma unroll
        for (int ks = 0; ks < 4; ks++) {
            uint32_t a[4];
            ldsm_x4(a, sb + PJ_WS + aoffL + (kc * 64 + ks * 16) * 2);
#pragma unroll
            for (int nt2 = 0; nt2 < 8; nt2++) {
                uint32_t bf[4];
                ldsm_x4(bf, xb32 + boffL + (wn * 128 + nt2 * 16) * 144 + ks * 32);
                mma16(acc[2 * nt2], a, bf[0], bf[2]);
                mma16(acc[2 * nt2 + 1], a, bf[1], bf[3]);
            }
        }
        __syncthreads();
    }

    // epilogue: + bias, fp16 pairs
    const int m0 = rowbase + wm * 16 + lq, m1 = m0 + 8;
    const float bias0 = g_bcat[m0], bias1 = g_bcat[m1];
    __half* og = g_QKV16 + (size_t)b * ROWS * NN;
#pragma unroll
    for (int nt = 0; nt < 16; nt++) {
        int n = nbase + wn * 128 + nt * 8 + 2 * lt4;
        *(__half2*)(og + (size_t)m0 * NN + n) = __floats2half2_rn(acc[nt][0] + bias0, acc[nt][1] + bias0);
        *(__half2*)(og + (size_t)m1 * NN + n) = __floats2half2_rn(acc[nt][2] + bias1, acc[nt][3] + bias1);
    }
}

// ===========================================================================
// Kernel 3: fp16 flash attention with lazy online-softmax rescale.
// CTA = (batch, 128-q tile), 8 warps.
//  S: warp w owns rows [16w,16w+16); PV: warp w owns channels [32w,32w+32).
// ===========================================================================
#define BQ 128
#define BK 64
#define NT (NN / BK)
#define QSTH_B 272        // Q rows (c): 128 q halves + pad -> 272B (68 words, 4r mod 32)
#define KVTH_B 144        // K/V/P rows: 64 halves + pad -> 144B

#define SM_Q    0          // [32c][128q]          8704
#define SM_K0   8704       // [32c][64m]           4608
#define SM_K1   13312
#define SM_V0   17920      // [256ch][64m]         36864
#define SM_V1   54784
#define SM_P    91648      // [128q][64m]          18432
#define SM_MREF 110080     // float[128]
#define SM_ALPH 110592     // float[128]
#define SM_LROW 111104     // float[128]
#define SM_FLAG 111616     // int
#define SMEM_AT 111648

__global__ __launch_bounds__(256, 1) void attn_kernel(const float* __restrict__ x,
                                                      const float* __restrict__ gamma_p,
                                                      float* __restrict__ out) {
    extern __shared__ __align__(128) char smem[];
    const uint32_t sb = smem_to_u32(smem);
    float* mref  = (float*)(smem + SM_MREF);
    float* alph  = (float*)(smem + SM_ALPH);
    float* lrow  = (float*)(smem + SM_LROW);
    int*   flagp = (int*)(smem + SM_FLAG);

    const int tid = threadIdx.x;
    const int w = tid >> 5, lane = tid & 31;
    const int lq = lane >> 2, lt4 = lane & 3;
    const int b = blockIdx.y;
    const int qbase = blockIdx.x * BQ;

    const __half* Qg = g_QKV16 + (size_t)b * ROWS * NN;
    const __half* Kg = Qg + (size_t)CI * NN;
    const __half* Vg = Qg + (size_t)2 * CI * NN;

    // stage Q + K/V tile 0
#pragma unroll
    for (int i = 0; i < 2; i++) {
        int idx = tid + i * 256, c = idx >> 4, j = idx & 15;
        cp16(sb + SM_Q + c * QSTH_B + j * 16, Qg + (size_t)c * NN + qbase + j * 8);
    }
    {
        int c = tid >> 3, j = tid & 7;
        cp16(sb + SM_K0 + c * KVTH_B + j * 16, Kg + (size_t)c * NN + j * 8);
#pragma unroll
        for (int i = 0; i < 8; i++) {
            int idx = tid + i * 256, ch = idx >> 3, jj = idx & 7;
            cp16(sb + SM_V0 + ch * KVTH_B + jj * 16, Vg + (size_t)ch * NN + jj * 8);
        }
    }
    CP_COMMIT();
    if (tid < BQ) mref[tid] = -1e30f;
    if (tid == 0) *flagp = 0;
    CP_WAIT(0);
    __syncthreads();

    // per-thread ldmatrix address components
    const uint32_t xtr = (uint32_t)(((lane >> 4) * 8 + (lane & 7)));          // trans: source row
    const uint32_t ytr = (uint32_t)(((lane >> 3) & 1) * 16);                  // trans: col byte
    const uint32_t ant = (uint32_t)((lane & 15) * KVTH_B + (lane >> 4) * 16); // non-trans A (P)
    const uint32_t bnt = (uint32_t)((((lane >> 3) & 1) * 8 + (lane & 7)) * KVTH_B + (lane >> 4) * 16);

    // preload Q A-fragments
    uint32_t aq[2][4];
#pragma unroll
    for (int ks = 0; ks < 2; ks++)
        ldsm_x4t(aq[ks], sb + SM_Q + (ks * 16 + xtr) * QSTH_B + w * 32 + ytr);

    float Oacc[128];
#pragma unroll
    for (int i = 0; i < 128; i++) Oacc[i] = 0.f;
    float l0 = 0.f, l1 = 0.f;
    const int row0 = w * 16 + lq, row1 = row0 + 8;

#pragma unroll 1
    for (int t = 0; t < NT; t++) {
        const int bi = t & 1;
        __syncthreads();                 // prev tile fully consumed
        if (tid == 0) *flagp = 0;
        if (t + 1 < NT) {
            const int kt = (t + 1) * BK;
            uint32_t kd = sb + ((t + 1) & 1 ? SM_K1 : SM_K0);
            uint32_t vd = sb + ((t + 1) & 1 ? SM_V1 : SM_V0);
            int c = tid >> 3, j = tid & 7;
            cp16(kd + c * KVTH_B + j * 16, Kg + (size_t)c * NN + kt + j * 8);
#pragma unroll
            for (int i = 0; i < 8; i++) {
                int idx = tid + i * 256, ch = idx >> 3, jj = idx & 7;
                cp16(vd + ch * KVTH_B + jj * 16, Vg + (size_t)ch * NN + kt + jj * 8);
            }
            CP_COMMIT();
            CP_WAIT(1);
        } else {
            CP_WAIT(0);
        }
        __syncthreads();                 // tile t staged + flag reset visible

        // ---- S = Q K^T (this warp's 16 rows)
        const uint32_t kbuf = sb + (bi ? SM_K1 : SM_K0);
        float sacc[8][4];
#pragma unroll
        for (int nt = 0; nt < 8; nt++)
#pragma unroll
            for (int e = 0; e < 4; e++) sacc[nt][e] = 0.f;
#pragma unroll
        for (int ks = 0; ks < 2; ks++) {
#pragma unroll
            for (int nt2 = 0; nt2 < 4; nt2++) {
                uint32_t kb[4];
                ldsm_x4t(kb, kbuf + (ks * 16 + xtr) * KVTH_B + nt2 * 32 + ytr);
                mma16(sacc[2 * nt2], aq[ks], kb[0], kb[2]);
                mma16(sacc[2 * nt2 + 1], aq[ks], kb[1], kb[3]);
            }
        }

        // ---- lazy online softmax stats
        float tm0 = -1e30f, tm1 = -1e30f;
#pragma unroll
        for (int nt = 0; nt < 8; nt++) {
            tm0 = fmaxf(tm0, fmaxf(sacc[nt][0], sacc[nt][1]));
            tm1 = fmaxf(tm1, fmaxf(sacc[nt][2], sacc[nt][3]));
        }
        tm0 = fmaxf(tm0, __shfl_xor_sync(0xffffffffu, tm0, 1));
        tm0 = fmaxf(tm0, __shfl_xor_sync(0xffffffffu, tm0, 2));
        tm1 = fmaxf(tm1, __shfl_xor_sync(0xffffffffu, tm1, 1));
        tm1 = fmaxf(tm1, __shfl_xor_sync(0xffffffffu, tm1, 2));
        const float mold0 = mref[row0], mold1 = mref[row1];
        const float mnew0 = (tm0 > mold0 + 6.f) ? tm0 : mold0;
        const float mnew1 = (tm1 > mold1 + 6.f) ? tm1 : mold1;
        const float alpha0 = __expf(mold0 - mnew0);   // 1 when unchanged; 0 on first tile
        const float alpha1 = __expf(mold1 - mnew1);
        if (lt4 == 0) {
            mref[row0] = mnew0; alph[row0] = alpha0;
            mref[row1] = mnew1; alph[row1] = alpha1;
            if (mnew0 != mold0 || mnew1 != mold1) *flagp = 1;
        }
        // ---- exp + store P (fp16)
        float ts0 = 0.f, ts1 = 0.f;
#pragma unroll
        for (int nt = 0; nt < 8; nt++) {
            float p0 = __expf(sacc[nt][0] - mnew0);
            float p1 = __expf(sacc[nt][1] - mnew0);
            float p2 = __expf(sacc[nt][2] - mnew1);
            float p3 = __expf(sacc[nt][3] - mnew1);
            ts0 += p0 + p1; ts1 += p2 + p3;
            int mcol = nt * 8 + 2 * lt4;
            *(__half2*)(smem + SM_P + row0 * KVTH_B + mcol * 2) = __floats2half2_rn(p0, p1);
            *(__half2*)(smem + SM_P + row1 * KVTH_B + mcol * 2) = __floats2half2_rn(p2, p3);
        }
        l0 = l0 * alpha0 + ts0;
        l1 = l1 * alpha1 + ts1;
        __syncthreads();                 // P + stats visible

        // ---- O (+rescale) += P V^T  (this warp's 32 channels)
        if (*flagp) {
#pragma unroll
            for (int mt = 0; mt < 8; mt++) {
                float a0 = alph[mt * 16 + lq], a1 = alph[mt * 16 + lq + 8];
#pragma unroll
                for (int nt = 0; nt < 4; nt++) {
                    float* o = &Oacc[(mt * 4 + nt) * 4];
                    o[0] *= a0; o[1] *= a0; o[2] *= a1; o[3] *= a1;
                }
            }
        }
        const uint32_t vbuf = sb + (bi ? SM_V1 : SM_V0);
#pragma unroll
        for (int ks = 0; ks < 4; ks++) {
            uint32_t vb0[4], vb1[4];
            {
                uint32_t tr[4];
                ldsm_x4(tr, vbuf + bnt + (w * 32) * KVTH_B + ks * 32);
                vb0[0] = tr[0]; vb0[1] = tr[1]; vb1[0] = tr[2]; vb1[1] = tr[3];
                ldsm_x4(tr, vbuf + bnt + (w * 32 + 16) * KVTH_B + ks * 32);
                vb0[2] = tr[0]; vb0[3] = tr[1]; vb1[2] = tr[2]; vb1[3] = tr[3];
            }
#pragma unroll
            for (int mt = 0; mt < 8; mt++) {
                uint32_t a[4];
                ldsm_x4(a, sb + SM_P + ant + (mt * 16) * KVTH_B + ks * 32);
#pragma unroll
                for (int nt = 0; nt < 4; nt++)
                    mma16(&Oacc[(mt * 4 + nt) * 4], a, vb0[nt], vb1[nt]);
            }
        }
    }

    // ---- epilogue
    __syncthreads();
    l0 += __shfl_xor_sync(0xffffffffu, l0, 1);
    l0 += __shfl_xor_sync(0xffffffffu, l0, 2);
    l1 += __shfl_xor_sync(0xffffffffu, l1, 1);
    l1 += __shfl_xor_sync(0xffffffffu, l1, 2);
    if (lt4 == 0) { lrow[row0] = l0; lrow[row1] = l1; }
    __syncthreads();

    const float g = gamma_p[0];
    const float* xb = x + (size_t)b * CC * NN;
    float* ob = out + (size_t)b * CC * NN;
#pragma unroll
    for (int mt = 0; mt < 8; mt++) {
        float s0 = g / lrow[mt * 16 + lq];
        float s1 = g / lrow[mt * 16 + lq + 8];
        int na = qbase + mt * 16 + lq;
#pragma unroll
        for (int nt = 0; nt < 4; nt++) {
            int ch = w * 32 + nt * 8 + 2 * lt4;
            const float* o = &Oacc[(mt * 4 + nt) * 4];
            size_t i00 = (size_t)ch * NN + na;
            size_t i10 = (size_t)(ch + 1) * NN + na;
            ob[i00] = o[0] * s0 + xb[i00];
            ob[i10] = o[1] * s0 + xb[i10];
            ob[i00 + 8] = o[2] * s1 + xb[i00 + 8];
            ob[i10 + 8] = o[3] * s1 + xb[i10 + 8];
        }
    }
}

// ===========================================================================
// Launch
// ===========================================================================
extern "C" void kernel_launch(void* const* d_in, const int* in_sizes, int n_in,
                              void* d_out, int out_size) {
    const float* x  = (const float*)d_in[0];
    const float* Wq = (const float*)d_in[1];
    const float* bq = (const float*)d_in[2];
    const float* Wk = (const float*)d_in[3];
    const float* bk = (const float*)d_in[4];
    const float* Wv = (const float*)d_in[5];
    const float* bv = (const float*)d_in[6];
    const float* gamma = (const float*)d_in[7];
    float* out = (float*)d_out;

    static int cfg = 0;
    if (!cfg) {
        cudaFuncSetAttribute(proj_kernel, cudaFuncAttributeMaxDynamicSharedMemorySize, PJ_SMEM);
        cudaFuncSetAttribute(attn_kernel, cudaFuncAttributeMaxDynamicSharedMemorySize, SMEM_AT);
        cfg = 1;
    }

    prep_kernel<<<(ROWS * CC + 255) / 256, 256>>>(Wq, bq, Wk, bk, Wv, bv);

    dim3 cgrid(NN / 32, CC / 32, BB);
    convx_kernel<<<cgrid, dim3(32, 8)>>>(x);

    dim3 pgrid(NN / 256, ROWS / 64, BB);
    proj_kernel<<<pgrid, 256, PJ_SMEM>>>();

    dim3 agrid(NN / BQ, BB);
    attn_kernel<<<agrid, 256, SMEM_AT>>>(x, gamma, out);
}

// round 5
// speedup vs baseline: 8.3341x; 1.0587x over previous
#include <cuda_runtime.h>
#include <cuda_fp16.h>
#include <cstdint>
#include <math.h>

#define BB 4
#define CC 256
#define CI 32
#define NN 4096
#define ROWS 320

__device__ float g_bcat[ROWS];
__device__ __align__(256) __half g_W16[ROWS * CC];
__device__ __align__(256) __half g_xT[(size_t)BB * NN * CC];
__device__ __align__(256) __half g_QKV16[(size_t)BB * ROWS * NN];

// ===========================================================================
// Portable PTX helpers
// ===========================================================================
__device__ __forceinline__ uint32_t smem_to_u32(const void* p) {
    uint32_t a;
    asm("{ .reg .u64 t; cvta.to.shared.u64 t, %1; cvt.u32.u64 %0, t; }" : "=r"(a) : "l"(p));
    return a;
}
__device__ __forceinline__ void cp16(uint32_t dst, const void* src) {
    asm volatile("cp.async.ca.shared.global [%0], [%1], 16;" :: "r"(dst), "l"(src) : "memory");
}
#define CP_COMMIT() asm volatile("cp.async.commit_group;" ::: "memory")
#define CP_WAIT(n)  asm volatile("cp.async.wait_group %0;" :: "n"(n) : "memory")
#define BAR_SYNC(id, n)   asm volatile("bar.sync %0, %1;"   :: "r"(id), "r"(n) : "memory")
#define BAR_ARRIVE(id, n) asm volatile("bar.arrive %0, %1;" :: "r"(id), "r"(n) : "memory")

__device__ __forceinline__ void ldsm_x4(uint32_t* r, uint32_t addr) {
    asm volatile("ldmatrix.sync.aligned.m8n8.x4.shared.b16 {%0,%1,%2,%3}, [%4];"
        : "=r"(r[0]), "=r"(r[1]), "=r"(r[2]), "=r"(r[3]) : "r"(addr));
}
__device__ __forceinline__ void ldsm_x4t(uint32_t* r, uint32_t addr) {
    asm volatile("ldmatrix.sync.aligned.m8n8.x4.trans.shared.b16 {%0,%1,%2,%3}, [%4];"
        : "=r"(r[0]), "=r"(r[1]), "=r"(r[2]), "=r"(r[3]) : "r"(addr));
}
__device__ __forceinline__ void mma16(float* d, const uint32_t* a, uint32_t b0, uint32_t b1) {
    asm volatile(
        "mma.sync.aligned.m16n8k16.row.col.f32.f16.f16.f32 "
        "{%0,%1,%2,%3}, {%4,%5,%6,%7}, {%8,%9}, {%0,%1,%2,%3};"
        : "+f"(d[0]), "+f"(d[1]), "+f"(d[2]), "+f"(d[3])
        : "r"(a[0]), "r"(a[1]), "r"(a[2]), "r"(a[3]), "r"(b0), "r"(b1));
}

// ===========================================================================
// Kernel 0: concat + fp16-convert weights
// ===========================================================================
__global__ void prep_kernel(const float* __restrict__ Wq, const float* __restrict__ bq,
                            const float* __restrict__ Wk, const float* __restrict__ bk,
                            const float* __restrict__ Wv, const float* __restrict__ bv) {
    int i = blockIdx.x * blockDim.x + threadIdx.x;
    if (i < CI * CC)            g_W16[i] = __float2half(Wq[i]);
    else if (i < 2 * CI * CC)   g_W16[i] = __float2half(Wk[i - CI * CC]);
    else if (i < ROWS * CC)     g_W16[i] = __float2half(Wv[i - 2 * CI * CC]);
    if (i < CI)                 g_bcat[i] = bq[i];
    else if (i < 2 * CI)        g_bcat[i] = bk[i - CI];
    else if (i < ROWS)          g_bcat[i] = bv[i - 2 * CI];
}

// ===========================================================================
// Kernel 1: transpose+convert x -> g_xT[b][n][c] fp16
// ===========================================================================
__global__ void convx_kernel(const float* __restrict__ x) {
    __shared__ __half t[32][33];
    const int b = blockIdx.z, nb = blockIdx.x * 32, cb = blockIdx.y * 32;
    const int tx = threadIdx.x, ty = threadIdx.y;
    const float* xb = x + (size_t)b * CC * NN;
#pragma unroll
    for (int i = 0; i < 4; i++)
        t[ty + i * 8][tx] = __float2half(xb[(size_t)(cb + ty + i * 8) * NN + nb + tx]);
    __syncthreads();
    __half* dst = g_xT + (size_t)b * NN * CC;
#pragma unroll
    for (int i = 0; i < 4; i++)
        dst[(size_t)(nb + ty + i * 8) * CC + cb + tx] = t[tx][ty + i * 8];
}

// ===========================================================================
// Kernel 2: QKV projection via fp16 mma (unchanged from R4)
// ===========================================================================
#define PJ_WS 0
#define PJ_X0 33792
#define PJ_X1 70656
#define PJ_SMEM 107520

__global__ __launch_bounds__(256) void proj_kernel() {
    extern __shared__ __align__(128) char psm[];
    const uint32_t sb = smem_to_u32(psm);
    const int tid = threadIdx.x;
    const int w = tid >> 5, lane = tid & 31;
    const int lq = lane >> 2, lt4 = lane & 3;
    const int wm = w & 3, wn = w >> 2;
    const int b = blockIdx.z;
    const int rowbase = blockIdx.y * 64;
    const int nbase = blockIdx.x * 256;

    const __half* Wg = g_W16 + (size_t)rowbase * CC;
#pragma unroll
    for (int i = 0; i < 8; i++) {
        int idx = tid + i * 256, r = idx >> 5, ch = idx & 31;
        cp16(sb + PJ_WS + r * 528 + ch * 16, Wg + (size_t)r * CC + ch * 8);
    }
    const __half* Xg = g_xT + ((size_t)b * NN + nbase) * CC;
#pragma unroll
    for (int i = 0; i < 8; i++) {
        int idx = tid + i * 256, n = idx >> 3, j = idx & 7;
        cp16(sb + PJ_X0 + n * 144 + j * 16, Xg + (size_t)n * CC + j * 8);
    }
    CP_COMMIT();

    float acc[16][4];
#pragma unroll
    for (int i = 0; i < 16; i++)
#pragma unroll
        for (int e = 0; e < 4; e++) acc[i][e] = 0.f;

    const uint32_t aoffL = (uint32_t)((wm * 16 + (lane & 15)) * 528 + (lane >> 4) * 16);
    const uint32_t boffL = (uint32_t)((((lane >> 3) & 1) * 8 + (lane & 7)) * 144 + (lane >> 4) * 16);

#pragma unroll
    for (int kc = 0; kc < 4; kc++) {
        if (kc + 1 < 4) {
            uint32_t xdst = sb + ((kc + 1) & 1 ? PJ_X1 : PJ_X0);
#pragma unroll
            for (int i = 0; i < 8; i++) {
                int idx = tid + i * 256, n = idx >> 3, j = idx & 7;
                cp16(xdst + n * 144 + j * 16, Xg + (size_t)n * CC + (kc + 1) * 64 + j * 8);
            }
            CP_COMMIT();
            CP_WAIT(1);
        } else {
            CP_WAIT(0);
        }
        __syncthreads();
        const uint32_t xb32 = sb + (kc & 1 ? PJ_X1 : PJ_X0);
#pragma unroll
        for (int ks = 0; ks < 4; ks++) {
            uint32_t a[4];
            ldsm_x4(a, sb + PJ_WS + aoffL + (kc * 64 + ks * 16) * 2);
#pragma unroll
            for (int nt2 = 0; nt2 < 8; nt2++) {
                uint32_t bf[4];
                ldsm_x4(bf, xb32 + boffL + (wn * 128 + nt2 * 16) * 144 + ks * 32);
                mma16(acc[2 * nt2], a, bf[0], bf[2]);
                mma16(acc[2 * nt2 + 1], a, bf[1], bf[3]);
            }
        }
        __syncthreads();
    }

    const int m0 = rowbase + wm * 16 + lq, m1 = m0 + 8;
    const float bias0 = g_bcat[m0], bias1 = g_bcat[m1];
    __half* og = g_QKV16 + (size_t)b * ROWS * NN;
#pragma unroll
    for (int nt = 0; nt < 16; nt++) {
        int n = nbase + wn * 128 + nt * 8 + 2 * lt4;
        *(__half2*)(og + (size_t)m0 * NN + n) = __floats2half2_rn(acc[nt][0] + bias0, acc[nt][1] + bias0);
        *(__half2*)(og + (size_t)m1 * NN + n) = __floats2half2_rn(acc[nt][2] + bias1, acc[nt][3] + bias1);
    }
}

// ===========================================================================
// Kernel 3: warp-specialized fp16 flash attention.
// 384 threads: warps 0-3 = S-warps (S, softmax, P), warps 4-11 = V-warps (PV).
// P, alpha, flag double-buffered; handoff via named barriers.
//  S-warp sw owns rows [32sw, 32sw+32).  V-warp vw owns channels [32vw, 32vw+32).
// ===========================================================================
#define BQ 128
#define BK 64
#define NT (NN / BK)
#define QST 272
#define KVT 144

#define SM_Q    0
#define SM_K0   8704
#define SM_K1   13312
#define SM_V0   17920
#define SM_V1   54784
#define SM_P0   91648
#define SM_P1   110080
#define SM_MREF 128512
#define SM_ALPH 129024     // float[2][128]
#define SM_LROW 130048
#define SM_FLAG 130560     // int[8]
#define SMEM_AT 130592

#define BID_PRDY 1   /* +bi : P(bi) ready   (count 384) */
#define BID_PFRE 3   /* +bi : P(bi) free    (count 384) */
#define BID_SBAR 5   /* S-warps internal    (count 128) */
#define BID_VBAR 6   /* V-warps internal    (count 256) */

__global__ __launch_bounds__(384, 1) void attn_kernel(const float* __restrict__ x,
                                                      const float* __restrict__ gamma_p,
                                                      float* __restrict__ out) {
    extern __shared__ __align__(128) char smem[];
    const uint32_t sb = smem_to_u32(smem);
    float* mref = (float*)(smem + SM_MREF);
    float* alph = (float*)(smem + SM_ALPH);
    float* lrow = (float*)(smem + SM_LROW);
    int* flagv  = (int*)(smem + SM_FLAG);

    const int tid = threadIdx.x;
    const int w = tid >> 5, lane = tid & 31;
    const int lq = lane >> 2, lt4 = lane & 3;
    const int b = blockIdx.y;
    const int qbase = blockIdx.x * BQ;

    const __half* Qg = g_QKV16 + (size_t)b * ROWS * NN;
    const __half* Kg = Qg + (size_t)CI * NN;
    const __half* Vg = Qg + (size_t)2 * CI * NN;

    // ---- prologue staging: Q (all), K0 (S-threads), V0 (V-threads)
    for (int idx = tid; idx < 512; idx += 384) {
        int c = idx >> 4, j = idx & 15;
        cp16(sb + SM_Q + c * QST + j * 16, Qg + (size_t)c * NN + qbase + j * 8);
    }
    if (tid < 128) {
#pragma unroll
        for (int i = 0; i < 2; i++) {
            int idx = tid + i * 128, c = idx >> 3, j = idx & 7;
            cp16(sb + SM_K0 + c * KVT + j * 16, Kg + (size_t)c * NN + j * 8);
        }
    } else {
        int vt = tid - 128;
#pragma unroll
        for (int i = 0; i < 8; i++) {
            int idx = vt + i * 256, ch = idx >> 3, j = idx & 7;
            cp16(sb + SM_V0 + ch * KVT + j * 16, Vg + (size_t)ch * NN + j * 8);
        }
    }
    CP_COMMIT();
    if (tid < BQ) mref[tid] = -1e30f;
    CP_WAIT(0);
    __syncthreads();

    // ldmatrix lane addressing
    const uint32_t xtr = (uint32_t)((lane >> 4) * 8 + (lane & 7));
    const uint32_t ytr = (uint32_t)(((lane >> 3) & 1) * 16);
    const uint32_t ant = (uint32_t)((lane & 15) * KVT + (lane >> 4) * 16);
    const uint32_t bnt = (uint32_t)((((lane >> 3) & 1) * 8 + (lane & 7)) * KVT + (lane >> 4) * 16);

    if (w < 4) {
        // =================== S-warps ===================
        const int sw = w;
        uint32_t aq[2][2][4];
#pragma unroll
        for (int rg = 0; rg < 2; rg++)
#pragma unroll
            for (int ks = 0; ks < 2; ks++)
                ldsm_x4t(aq[rg][ks], sb + SM_Q + (ks * 16 + xtr) * QST + (sw * 32 + rg * 16) * 2 + ytr);

        float l00 = 0.f, l01 = 0.f, l10 = 0.f, l11 = 0.f;

#pragma unroll 1
        for (int t = 0; t < NT; t++) {
            const int bi = t & 1;
            BAR_SYNC(BID_SBAR, 128);             // all S-warps done reading K((t-1)) buffer
            if (t + 1 < NT) {
                uint32_t kd = sb + ((t + 1) & 1 ? SM_K1 : SM_K0);
                const int kt1 = (t + 1) * BK;
#pragma unroll
                for (int i = 0; i < 2; i++) {
                    int idx = tid + i * 128, c = idx >> 3, j = idx & 7;
                    cp16(kd + c * KVT + j * 16, Kg + (size_t)c * NN + kt1 + j * 8);
                }
                CP_COMMIT();
                CP_WAIT(1);
            } else {
                CP_WAIT(0);
            }
            BAR_SYNC(BID_SBAR, 128);             // K(t) visible to all S-warps

            const uint32_t kbuf = sb + (bi ? SM_K1 : SM_K0);
            float sacc[2][8][4];
#pragma unroll
            for (int rg = 0; rg < 2; rg++)
#pragma unroll
                for (int nt = 0; nt < 8; nt++)
#pragma unroll
                    for (int e = 0; e < 4; e++) sacc[rg][nt][e] = 0.f;
#pragma unroll
            for (int ks = 0; ks < 2; ks++) {
#pragma unroll
                for (int nt2 = 0; nt2 < 4; nt2++) {
                    uint32_t kb[4];
                    ldsm_x4t(kb, kbuf + (ks * 16 + xtr) * KVT + nt2 * 32 + ytr);
#pragma unroll
                    for (int rg = 0; rg < 2; rg++) {
                        mma16(sacc[rg][2 * nt2], aq[rg][ks], kb[0], kb[2]);
                        mma16(sacc[rg][2 * nt2 + 1], aq[rg][ks], kb[1], kb[3]);
                    }
                }
            }

            BAR_SYNC(BID_PFRE + bi, 384);        // V-warps released P(bi)

            const uint32_t pbuf = sb + (bi ? SM_P1 : SM_P0);
            bool anyflag = false;
#pragma unroll
            for (int rg = 0; rg < 2; rg++) {
                const int row0 = sw * 32 + rg * 16 + lq, row1 = row0 + 8;
                float tm0 = -1e30f, tm1 = -1e30f;
#pragma unroll
                for (int nt = 0; nt < 8; nt++) {
                    tm0 = fmaxf(tm0, fmaxf(sacc[rg][nt][0], sacc[rg][nt][1]));
                    tm1 = fmaxf(tm1, fmaxf(sacc[rg][nt][2], sacc[rg][nt][3]));
                }
                tm0 = fmaxf(tm0, __shfl_xor_sync(0xffffffffu, tm0, 1));
                tm0 = fmaxf(tm0, __shfl_xor_sync(0xffffffffu, tm0, 2));
                tm1 = fmaxf(tm1, __shfl_xor_sync(0xffffffffu, tm1, 1));
                tm1 = fmaxf(tm1, __shfl_xor_sync(0xffffffffu, tm1, 2));
                const float mold0 = mref[row0], mold1 = mref[row1];
                const float mnew0 = (tm0 > mold0 + 6.f) ? tm0 : mold0;
                const float mnew1 = (tm1 > mold1 + 6.f) ? tm1 : mold1;
                const float alpha0 = __expf(mold0 - mnew0);
                const float alpha1 = __expf(mold1 - mnew1);
                if (lt4 == 0) {
                    mref[row0] = mnew0; alph[bi * 128 + row0] = alpha0;
                    mref[row1] = mnew1; alph[bi * 128 + row1] = alpha1;
                }
                anyflag |= (mnew0 != mold0) | (mnew1 != mold1);
                float ts0 = 0.f, ts1 = 0.f;
#pragma unroll
                for (int nt = 0; nt < 8; nt++) {
                    float p0 = __expf(sacc[rg][nt][0] - mnew0);
                    float p1 = __expf(sacc[rg][nt][1] - mnew0);
                    float p2 = __expf(sacc[rg][nt][2] - mnew1);
                    float p3 = __expf(sacc[rg][nt][3] - mnew1);
                    ts0 += p0 + p1; ts1 += p2 + p3;
                    int mb = (nt * 8 + 2 * lt4) * 2;
                    *(__half2*)(smem + (pbuf - sb) + row0 * KVT + mb) = __floats2half2_rn(p0, p1);
                    *(__half2*)(smem + (pbuf - sb) + row1 * KVT + mb) = __floats2half2_rn(p2, p3);
                }
                if (rg == 0) { l00 = l00 * alpha0 + ts0; l01 = l01 * alpha1 + ts1; }
                else         { l10 = l10 * alpha0 + ts0; l11 = l11 * alpha1 + ts1; }
            }
            int any = __any_sync(0xffffffffu, anyflag);
            if (lane == 0) flagv[bi * 4 + sw] = any;
            BAR_ARRIVE(BID_PRDY + bi, 384);      // publish P(bi)
        }

        // final l
        l00 += __shfl_xor_sync(0xffffffffu, l00, 1); l00 += __shfl_xor_sync(0xffffffffu, l00, 2);
        l01 += __shfl_xor_sync(0xffffffffu, l01, 1); l01 += __shfl_xor_sync(0xffffffffu, l01, 2);
        l10 += __shfl_xor_sync(0xffffffffu, l10, 1); l10 += __shfl_xor_sync(0xffffffffu, l10, 2);
        l11 += __shfl_xor_sync(0xffffffffu, l11, 1); l11 += __shfl_xor_sync(0xffffffffu, l11, 2);
        if (lt4 == 0) {
            lrow[sw * 32 + lq] = l00;       lrow[sw * 32 + lq + 8] = l01;
            lrow[sw * 32 + 16 + lq] = l10;  lrow[sw * 32 + 16 + lq + 8] = l11;
        }
        __syncthreads();
        // S-warps done (V-warps do the epilogue)
    } else {
        // =================== V-warps ===================
        const int vw = w - 4;
        BAR_ARRIVE(BID_PFRE + 0, 384);           // P buffers initially free
        BAR_ARRIVE(BID_PFRE + 1, 384);

        float Oacc[128];
#pragma unroll
        for (int i = 0; i < 128; i++) Oacc[i] = 0.f;

#pragma unroll 1
        for (int t = 0; t < NT; t++) {
            const int bi = t & 1;
            BAR_SYNC(BID_VBAR, 256);             // all V-warps done reading V(t-1) buffer
            if (t + 1 < NT) {
                uint32_t vd = sb + ((t + 1) & 1 ? SM_V1 : SM_V0);
                const int kt1 = (t + 1) * BK;
                int vt = tid - 128;
#pragma unroll
                for (int i = 0; i < 8; i++) {
                    int idx = vt + i * 256, ch = idx >> 3, j = idx & 7;
                    cp16(vd + ch * KVT + j * 16, Vg + (size_t)ch * NN + kt1 + j * 8);
                }
                CP_COMMIT();
                CP_WAIT(1);
            } else {
                CP_WAIT(0);
            }
            BAR_SYNC(BID_VBAR, 256);             // V(t) visible
            BAR_SYNC(BID_PRDY + bi, 384);        // P(bi) ready

            int flag = flagv[bi * 4] | flagv[bi * 4 + 1] | flagv[bi * 4 + 2] | flagv[bi * 4 + 3];
            if (flag) {
#pragma unroll
                for (int mt = 0; mt < 8; mt++) {
                    float a0 = alph[bi * 128 + mt * 16 + lq];
                    float a1 = alph[bi * 128 + mt * 16 + lq + 8];
#pragma unroll
                    for (int nt = 0; nt < 4; nt++) {
                        float* o = &Oacc[(mt * 4 + nt) * 4];
                        o[0] *= a0; o[1] *= a0; o[2] *= a1; o[3] *= a1;
                    }
                }
            }
            const uint32_t vbuf = sb + (bi ? SM_V1 : SM_V0);
            const uint32_t pbuf = sb + (bi ? SM_P1 : SM_P0);
#pragma unroll
            for (int ks = 0; ks < 4; ks++) {
                uint32_t vb0[4], vb1[4];
                {
                    uint32_t tr[4];
                    ldsm_x4(tr, vbuf + bnt + (vw * 32) * KVT + ks * 32);
                    vb0[0] = tr[0]; vb0[1] = tr[1]; vb1[0] = tr[2]; vb1[1] = tr[3];
                    ldsm_x4(tr, vbuf + bnt + (vw * 32 + 16) * KVT + ks * 32);
                    vb0[2] = tr[0]; vb0[3] = tr[1]; vb1[2] = tr[2]; vb1[3] = tr[3];
                }
#pragma unroll
                for (int mt = 0; mt < 8; mt++) {
                    uint32_t a[4];
                    ldsm_x4(a, pbuf + ant + (mt * 16) * KVT + ks * 32);
#pragma unroll
                    for (int nt = 0; nt < 4; nt++)
                        mma16(&Oacc[(mt * 4 + nt) * 4], a, vb0[nt], vb1[nt]);
                }
            }
            BAR_ARRIVE(BID_PFRE + bi, 384);      // release P(bi)
        }

        __syncthreads();                         // lrow final

        const float g = gamma_p[0];
        const float* xb = x + (size_t)b * CC * NN;
        float* ob = out + (size_t)b * CC * NN;
#pragma unroll
        for (int mt = 0; mt < 8; mt++) {
            float s0 = g / lrow[mt * 16 + lq];
            float s1 = g / lrow[mt * 16 + lq + 8];
            int na = qbase + mt * 16 + lq;
#pragma unroll
            for (int nt = 0; nt < 4; nt++) {
                int ch = vw * 32 + nt * 8 + 2 * lt4;
                const float* o = &Oacc[(mt * 4 + nt) * 4];
                size_t i00 = (size_t)ch * NN + na;
                size_t i10 = (size_t)(ch + 1) * NN + na;
                ob[i00] = o[0] * s0 + xb[i00];
                ob[i10] = o[1] * s0 + xb[i10];
                ob[i00 + 8] = o[2] * s1 + xb[i00 + 8];
                ob[i10 + 8] = o[3] * s1 + xb[i10 + 8];
            }
        }
    }
}

// ===========================================================================
// Launch
// ===========================================================================
extern "C" void kernel_launch(void* const* d_in, const int* in_sizes, int n_in,
                              void* d_out, int out_size) {
    const float* x  = (const float*)d_in[0];
    const float* Wq = (const float*)d_in[1];
    const float* bq = (const float*)d_in[2];
    const float* Wk = (const float*)d_in[3];
    const float* bk = (const float*)d_in[4];
    const float* Wv = (const float*)d_in[5];
    const float* bv = (const float*)d_in[6];
    const float* gamma = (const float*)d_in[7];
    float* out = (float*)d_out;

    static int cfg = 0;
    if (!cfg) {
        cudaFuncSetAttribute(proj_kernel, cudaFuncAttributeMaxDynamicSharedMemorySize, PJ_SMEM);
        cudaFuncSetAttribute(attn_kernel, cudaFuncAttributeMaxDynamicSharedMemorySize, SMEM_AT);
        cfg = 1;
    }

    prep_kernel<<<(ROWS * CC + 255) / 256, 256>>>(Wq, bq, Wk, bk, Wv, bv);

    dim3 cgrid(NN / 32, CC / 32, BB);
    convx_kernel<<<cgrid, dim3(32, 8)>>>(x);

    dim3 pgrid(NN / 256, ROWS / 64, BB);
    proj_kernel<<<pgrid, 256, PJ_SMEM>>>();

    dim3 agrid(NN / BQ, BB);
    attn_kernel<<<agrid, 384, SMEM_AT>>>(x, gamma, out);
}